// round 11
// baseline (speedup 1.0000x reference)
#include <cuda_runtime.h>
#include <cstdint>

// GCMCGraphConv: h[dst] = ci[dst] * sum_{e: dst[e]=dst} weight[src[e]] * cj[src[e]]
// dst-CSR build (hist -> fused two-level scan -> scatter) + node-parallel pull.
// Hist/build vectorized x4 for atomic-latency hiding. CSR packs {src, cj[src]}.

#define FEAT 128
#define N_MAX 131072
#define E_MAX 2097152
#define NB_MAX 128   // N_MAX / 1024

__device__ int  g_count[N_MAX];
__device__ int  g_off[N_MAX];        // block-local exclusive prefix; local-inclusive after build
__device__ int  g_bsum[NB_MAX];      // per-block totals
__device__ int  g_bsum_excl[NB_MAX]; // exclusive scan of block totals
__device__ int  g_arrive;            // scan last-block arrival counter
__device__ int2 g_csr[E_MAX];        // {src, __float_as_int(cj[src])}

__global__ void zero_count_kernel(int n) {
    int i = blockIdx.x * blockDim.x + threadIdx.x;
    if (i < n) g_count[i] = 0;
    if (i == 0) g_arrive = 0;
}

// 4 edges per thread: independent REDs in flight to hide atomic latency.
__global__ void hist_kernel(const int* __restrict__ dst, int n_edges) {
    int t = blockIdx.x * blockDim.x + threadIdx.x;
    int base = t * 4;
    if (base + 4 <= n_edges) {
        int4 d4 = *reinterpret_cast<const int4*>(dst + base);
        atomicAdd(&g_count[d4.x], 1);
        atomicAdd(&g_count[d4.y], 1);
        atomicAdd(&g_count[d4.z], 1);
        atomicAdd(&g_count[d4.w], 1);
    } else {
        for (int e = base; e < n_edges; e++) atomicAdd(&g_count[dst[e]], 1);
    }
}

// Fused two-level scan: block-local exclusive scan -> g_off, block totals -> g_bsum;
// the LAST block to finish also scans the (<=NB_MAX) block totals into g_bsum_excl.
__global__ void scan_kernel(int n, int nb) {
    __shared__ int wsum[32];
    __shared__ int is_last;
    int tid = threadIdx.x, lane = tid & 31, w = tid >> 5;
    int i = blockIdx.x * 1024 + tid;
    int v = (i < n) ? g_count[i] : 0;
    int x = v;
    #pragma unroll
    for (int o = 1; o < 32; o <<= 1) {
        int y = __shfl_up_sync(0xffffffffu, x, o);
        if (lane >= o) x += y;
    }
    if (lane == 31) wsum[w] = x;
    __syncthreads();
    if (w == 0) {
        int s = wsum[lane];
        #pragma unroll
        for (int o = 1; o < 32; o <<= 1) {
            int y = __shfl_up_sync(0xffffffffu, s, o);
            if (lane >= o) s += y;
        }
        wsum[lane] = s;
    }
    __syncthreads();
    int woff = w ? wsum[w - 1] : 0;
    if (i < n) g_off[i] = woff + x - v;              // exclusive within block
    if (tid == 1023) g_bsum[blockIdx.x] = woff + x;  // block total

    // last-block election
    __threadfence();
    if (tid == 0) {
        int ticket = atomicAdd(&g_arrive, 1);
        is_last = (ticket == nb - 1);
    }
    __syncthreads();
    if (!is_last) return;

    // this block scans the block totals (first 128 threads)
    if (tid < 128) {
        int lane2 = tid & 31, w2 = tid >> 5;
        int bv = (tid < nb) ? g_bsum[tid] : 0;
        int bx = bv;
        #pragma unroll
        for (int o = 1; o < 32; o <<= 1) {
            int y = __shfl_up_sync(0xffffffffu, bx, o);
            if (lane2 >= o) bx += y;
        }
        if (lane2 == 31) wsum[w2] = bx;
        __syncwarp();
        // combine 4 warp sums serially in warp 0 (cheap, nb<=128)
    }
    __syncthreads();
    if (tid < 128) {
        int lane2 = tid & 31, w2 = tid >> 5;
        // recompute inclusive within warp (registers lost across syncthreads? no - keep simple: redo)
        int bv = (tid < nb) ? g_bsum[tid] : 0;
        int bx = bv;
        #pragma unroll
        for (int o = 1; o < 32; o <<= 1) {
            int y = __shfl_up_sync(0xffffffffu, bx, o);
            if (lane2 >= o) bx += y;
        }
        int woff2 = 0;
        #pragma unroll
        for (int j = 0; j < 4; j++) if (j < w2) woff2 += wsum[j];
        g_bsum_excl[tid] = woff2 + bx - bv;
    }
}

// Scatter edges into CSR slots, packing {src, cj[src]}. 4 edges per thread.
__global__ void build_csr_kernel(const int* __restrict__ src,
                                 const int* __restrict__ dst,
                                 const float* __restrict__ cj,
                                 int n_edges) {
    int t = blockIdx.x * blockDim.x + threadIdx.x;
    int base = t * 4;
    if (base + 4 <= n_edges) {
        int4 d4 = *reinterpret_cast<const int4*>(dst + base);
        int4 s4 = *reinterpret_cast<const int4*>(src + base);
        // 4 independent returning atomics in flight
        int p0 = atomicAdd(&g_off[d4.x], 1);
        int p1 = atomicAdd(&g_off[d4.y], 1);
        int p2 = atomicAdd(&g_off[d4.z], 1);
        int p3 = atomicAdd(&g_off[d4.w], 1);
        float c0 = __ldg(&cj[s4.x]);
        float c1 = __ldg(&cj[s4.y]);
        float c2 = __ldg(&cj[s4.z]);
        float c3 = __ldg(&cj[s4.w]);
        g_csr[p0 + __ldg(&g_bsum_excl[d4.x >> 10])] = make_int2(s4.x, __float_as_int(c0));
        g_csr[p1 + __ldg(&g_bsum_excl[d4.y >> 10])] = make_int2(s4.y, __float_as_int(c1));
        g_csr[p2 + __ldg(&g_bsum_excl[d4.z >> 10])] = make_int2(s4.z, __float_as_int(c2));
        g_csr[p3 + __ldg(&g_bsum_excl[d4.w >> 10])] = make_int2(s4.w, __float_as_int(c3));
    } else {
        for (int e = base; e < n_edges; e++) {
            int d = dst[e];
            int pos = atomicAdd(&g_off[d], 1) + __ldg(&g_bsum_excl[d >> 10]);
            int s = src[e];
            g_csr[pos] = make_int2(s, __float_as_int(__ldg(&cj[s])));
        }
    }
}

__device__ __forceinline__ int seg_end(int node) {
    return __ldg(&g_off[node]) + __ldg(&g_bsum_excl[node >> 10]);
}

// One warp per dst node: accumulate in registers, single write per element.
__global__ void pull_kernel(const float* __restrict__ weight,
                            const float* __restrict__ ci,
                            float* __restrict__ h,
                            int n_nodes) {
    int node = (blockIdx.x * blockDim.x + threadIdx.x) >> 5;
    int lane = threadIdx.x & 31;
    if (node >= n_nodes) return;

    int start = node ? seg_end(node - 1) : 0;
    int end   = seg_end(node);

    float ax = 0.f, ay = 0.f, az = 0.f, aw = 0.f;
    int k = start;
    for (; k + 8 <= end; k += 8) {
        int2 p[8];
        #pragma unroll
        for (int j = 0; j < 8; j++) p[j] = __ldg(&g_csr[k + j]);
        #pragma unroll
        for (int j = 0; j < 8; j++) {
            float c = __int_as_float(p[j].y);
            float4 v = __ldg(reinterpret_cast<const float4*>(weight + (size_t)p[j].x * FEAT) + lane);
            ax += c * v.x; ay += c * v.y; az += c * v.z; aw += c * v.w;
        }
    }
    if (k + 4 <= end) {
        int2 p[4];
        #pragma unroll
        for (int j = 0; j < 4; j++) p[j] = __ldg(&g_csr[k + j]);
        #pragma unroll
        for (int j = 0; j < 4; j++) {
            float c = __int_as_float(p[j].y);
            float4 v = __ldg(reinterpret_cast<const float4*>(weight + (size_t)p[j].x * FEAT) + lane);
            ax += c * v.x; ay += c * v.y; az += c * v.z; aw += c * v.w;
        }
        k += 4;
    }
    for (; k < end; k++) {
        int2 p = __ldg(&g_csr[k]);
        float c = __int_as_float(p.y);
        float4 v = __ldg(reinterpret_cast<const float4*>(weight + (size_t)p.x * FEAT) + lane);
        ax += c * v.x; ay += c * v.y; az += c * v.z; aw += c * v.w;
    }

    float ciev = __ldg(&ci[node]);
    float4 r;
    r.x = ax * ciev; r.y = ay * ciev; r.z = az * ciev; r.w = aw * ciev;
    reinterpret_cast<float4*>(h + (size_t)node * FEAT)[lane] = r;
}

extern "C" void kernel_launch(void* const* d_in, const int* in_sizes, int n_in,
                              void* d_out, int out_size) {
    const float* weight = (const float*)d_in[0];
    const float* cj     = (const float*)d_in[1];
    const float* ci     = (const float*)d_in[2];
    const int*   src    = (const int*)d_in[3];
    const int*   dst    = (const int*)d_in[4];
    float* h = (float*)d_out;

    int n_nodes = in_sizes[1];   // cj has N elements
    int n_edges = in_sizes[3];
    int n_blocks_scan = (n_nodes + 1023) / 1024;

    // 1. zero per-node counters + arrival counter
    zero_count_kernel<<<(n_nodes + 255) / 256, 256>>>(n_nodes);

    // 2. histogram of dst, 4 edges/thread
    {
        int n_threads = (n_edges + 3) / 4;
        hist_kernel<<<(n_threads + 255) / 256, 256>>>(dst, n_edges);
    }

    // 3. fused two-level scan (last block scans block totals)
    scan_kernel<<<n_blocks_scan, 1024>>>(n_nodes, n_blocks_scan);

    // 4. scatter edges into CSR, 4 edges/thread
    {
        int n_threads = (n_edges + 3) / 4;
        build_csr_kernel<<<(n_threads + 255) / 256, 256>>>(src, dst, cj, n_edges);
    }

    // 5. node-parallel pull, one warp per node
    {
        long long total_threads = (long long)n_nodes * 32;
        int blocks = (int)((total_threads + 255) / 256);
        pull_kernel<<<blocks, 256>>>(weight, ci, h, n_nodes);
    }
}